// round 9
// baseline (speedup 1.0000x reference)
#include <cuda_runtime.h>
#include <cuda_bf16.h>

// LSTM: B=32768, T=28, IN=28, H=8, NC=10. Gate order i,j,f,o. Forget bias 1.0.
// R9: TWO samples per thread. R8 was smem-return-bandwidth bound (288
// broadcast LDS.128/step x 4 cyc of 128B/cyc crossbar each ~= the whole
// 111 us). Weights are sample-invariant, so each LDS.128 now feeds FMAs for
// 2 samples -> smem traffic halves. Segmented unroll-1 step loop retained
// (it is what keeps ptxas's scheduling window, and regs, bounded).

#define BTOT 32768
#define TSTEPS 28
#define INDIM 28
#define HID 8
#define NCLS 10
#define BLK 32
#define SPT 2    // samples per thread

typedef unsigned long long u64;

__device__ __forceinline__ u64 pack2(float x) {
    u64 r; unsigned xi = __float_as_uint(x);
    asm("mov.b64 %0, {%1, %1};" : "=l"(r) : "r"(xi));
    return r;
}

__device__ __forceinline__ u64 fma2(u64 a, u64 b, u64 c) {
    u64 d;
    asm("fma.rn.f32x2 %0, %1, %2, %3;" : "=l"(d) : "l"(a), "l"(b), "l"(c));
    return d;
}

__device__ __forceinline__ void unpack2(u64 v, float& lo, float& hi) {
    unsigned a, b;
    asm("mov.b64 {%0, %1}, %2;" : "=r"(a), "=r"(b) : "l"(v));
    lo = __uint_as_float(a);
    hi = __uint_as_float(b);
}

__device__ __forceinline__ float sigf(float x) {
    float e = __expf(-x);
    return __fdividef(1.0f, 1.0f + e);
}

__device__ __forceinline__ float tanh_exact(float x) {
    // tanh(x) = 1 - 2/(e^{2x}+1). Overflow of e -> +1; underflow -> -1. Both correct.
    float e = __expf(2.0f * x);
    return 1.0f - __fdividef(2.0f, e + 1.0f);
}

__global__ __launch_bounds__(BLK)
void lstm_kernel(const float* __restrict__ x,
                 const float* __restrict__ W,      // [36, 32] row-major
                 const float* __restrict__ bias,   // [32]
                 const float* __restrict__ ow,     // [8, 10]
                 const float* __restrict__ ob,     // [10]
                 float* __restrict__ out)          // [B, 10]
{
    // Row k occupies sW2[k*8 .. k*8+7]; quad q holds gate columns 4q..4q+3.
    __shared__ ulonglong2 sW2[(INDIM + HID) * 8];   // 36 rows * 128B
    __shared__ ulonglong2 sB2[8];
    __shared__ float sOW[HID * NCLS];
    __shared__ float sOB[NCLS];

    const int tid = threadIdx.x;
    {
        const u64* gW = (const u64*)W;
        u64* sw = (u64*)sW2;
        for (int i = tid; i < (INDIM + HID) * 16; i += BLK) sw[i] = gW[i];
        for (int i = tid; i < 16; i += BLK)         ((u64*)sB2)[i] = ((const u64*)bias)[i];
        for (int i = tid; i < HID * NCLS; i += BLK) sOW[i] = ow[i];
        for (int i = tid; i < NCLS; i += BLK)       sOB[i] = ob[i];
    }
    __syncthreads();

    const int base = blockIdx.x * (BLK * SPT) + tid;
    const float4* xp[SPT];
#pragma unroll
    for (int s = 0; s < SPT; s++)
        xp[s] = (const float4*)(x + (size_t)(base + s * BLK) * TSTEPS * INDIM);

    float c[SPT][HID];
    float4 hA[SPT], hB[SPT];   // h0..3, h4..7 per sample
#pragma unroll
    for (int s = 0; s < SPT; s++) {
#pragma unroll
        for (int u = 0; u < HID; u++) c[s][u] = 0.0f;
        hA[s] = make_float4(0, 0, 0, 0);
        hB[s] = make_float4(0, 0, 0, 0);
    }

#pragma unroll 1
    for (int t = 0; t < TSTEPS; t++) {
        u64 g[SPT][16];
#pragma unroll
        for (int q = 0; q < 8; q++) {
            ulonglong2 bq = sB2[q];
#pragma unroll
            for (int s = 0; s < SPT; s++) {
                g[s][2 * q] = bq.x; g[s][2 * q + 1] = bq.y;
            }
        }

        float4 cur[SPT];
#pragma unroll
        for (int s = 0; s < SPT; s++) cur[s] = xp[s][t * 7];

        // 9 segments: 0..6 -> x chunks (rows 4*seg..4*seg+3),
        // 7 -> hA (rows 28..31), 8 -> hB (rows 32..35).
#pragma unroll 1
        for (int seg = 0; seg < 9; seg++) {
            float4 nxt[SPT];
#pragma unroll
            for (int s = 0; s < SPT; s++) {
                if (seg < 6)       nxt[s] = xp[s][t * 7 + seg + 1];
                else if (seg == 6) nxt[s] = hA[s];
                else if (seg == 7) nxt[s] = hB[s];
                else               nxt[s] = cur[s];   // dead
            }

            const int krow = 4 * seg;
#pragma unroll
            for (int j = 0; j < 4; j++) {
                u64 xx[SPT];
#pragma unroll
                for (int s = 0; s < SPT; s++) {
                    float xs = (j == 0) ? cur[s].x : (j == 1) ? cur[s].y
                             : (j == 2) ? cur[s].z : cur[s].w;
                    xx[s] = pack2(xs);
                }
#pragma unroll
                for (int q = 0; q < 8; q++) {
                    ulonglong2 w = sW2[(krow + j) * 8 + q];   // one load, SPT samples
#pragma unroll
                    for (int s = 0; s < SPT; s++) {
                        g[s][2 * q]     = fma2(xx[s], w.x, g[s][2 * q]);
                        g[s][2 * q + 1] = fma2(xx[s], w.y, g[s][2 * q + 1]);
                    }
                }
            }
#pragma unroll
            for (int s = 0; s < SPT; s++) cur[s] = nxt[s];
        }

        // activations: cols 0..7=i, 8..15=j, 16..23=f, 24..31=o (pair p = cols 2p,2p+1)
#pragma unroll
        for (int s = 0; s < SPT; s++) {
            float ia[8], ja[8], fa[8], oa[8];
#pragma unroll
            for (int v = 0; v < 4; v++) {
                unpack2(g[s][v],      ia[2 * v], ia[2 * v + 1]);
                unpack2(g[s][4 + v],  ja[2 * v], ja[2 * v + 1]);
                unpack2(g[s][8 + v],  fa[2 * v], fa[2 * v + 1]);
                unpack2(g[s][12 + v], oa[2 * v], oa[2 * v + 1]);
            }
            float hn[8];
#pragma unroll
            for (int u = 0; u < HID; u++) {
                float ig = sigf(ia[u]);
                float jt = tanh_exact(ja[u]);
                float fg = sigf(fa[u] + 1.0f);   // forget bias
                float og = sigf(oa[u]);
                float cn = c[s][u] * fg + ig * jt;
                c[s][u] = cn;
                hn[u] = tanh_exact(cn) * og;
            }
            hA[s] = make_float4(hn[0], hn[1], hn[2], hn[3]);
            hB[s] = make_float4(hn[4], hn[5], hn[6], hn[7]);
        }
    }

    // Output projection: logits = h @ ow + ob
#pragma unroll
    for (int s = 0; s < SPT; s++) {
        float hf[8] = {hA[s].x, hA[s].y, hA[s].z, hA[s].w,
                       hB[s].x, hB[s].y, hB[s].z, hB[s].w};
        float* op = out + (size_t)(base + s * BLK) * NCLS;
#pragma unroll
        for (int n = 0; n < NCLS; n++) {
            float acc = sOB[n];
#pragma unroll
            for (int u = 0; u < HID; u++) acc += hf[u] * sOW[u * NCLS + n];
            op[n] = acc;
        }
    }
}

extern "C" void kernel_launch(void* const* d_in, const int* in_sizes, int n_in,
                              void* d_out, int out_size) {
    const float* x  = (const float*)d_in[0];
    const float* W  = (const float*)d_in[1];
    const float* bl = (const float*)d_in[2];
    const float* ow = (const float*)d_in[3];
    const float* ob = (const float*)d_in[4];
    float* out = (float*)d_out;

    lstm_kernel<<<BTOT / (BLK * SPT), BLK>>>(x, W, bl, ow, ob, out);
}

// round 11
// speedup vs baseline: 1.0749x; 1.0749x over previous
#include <cuda_runtime.h>
#include <cuda_bf16.h>

// LSTM: B=32768, T=28, IN=28, H=8, NC=10. Gate order i,j,f,o. Forget bias 1.0.
// R11 = R10 resubmit (R10 bench died to infra, no verdict).
// TWO LANES PER SAMPLE (lane parity = gate half). Even lane: cols 0..15
// (i,j gates); odd lane: cols 16..31 (f,o). 65536 threads -> 2048 warps
// (3.46/SMSP) fixes the occupancy bound; per-lane work halves (144 LDS.128 +
// 288 FFMA2 per step). Gate exchange = one shfl.xor(1) pair per hidden unit;
// both lanes then compute bit-identical c/h redundantly (no h broadcast).
// Activations exact (__expf + __fdividef) in uniform control flow with
// per-lane constants. Segmented unroll-1 step loop retained (reg control).

#define BTOT 32768
#define TSTEPS 28
#define INDIM 28
#define HID 8
#define NCLS 10
#define BLK 128

typedef unsigned long long u64;

__device__ __forceinline__ u64 pack2(float x) {
    u64 r; unsigned xi = __float_as_uint(x);
    asm("mov.b64 %0, {%1, %1};" : "=l"(r) : "r"(xi));
    return r;
}

__device__ __forceinline__ u64 fma2(u64 a, u64 b, u64 c) {
    u64 d;
    asm("fma.rn.f32x2 %0, %1, %2, %3;" : "=l"(d) : "l"(a), "l"(b), "l"(c));
    return d;
}

__device__ __forceinline__ void unpack2(u64 v, float& lo, float& hi) {
    unsigned a, b;
    asm("mov.b64 {%0, %1}, %2;" : "=r"(a), "=r"(b) : "l"(v));
    lo = __uint_as_float(a);
    hi = __uint_as_float(b);
}

__device__ __forceinline__ float tanh_exact(float x) {
    // tanh(x) = 1 - 2/(e^{2x}+1). Overflow of e -> +1; underflow -> -1.
    float e = __expf(2.0f * x);
    return 1.0f - __fdividef(2.0f, e + 1.0f);
}

__global__ __launch_bounds__(BLK)
void lstm_kernel(const float* __restrict__ x,
                 const float* __restrict__ W,      // [36, 32] row-major
                 const float* __restrict__ bias,   // [32]
                 const float* __restrict__ ow,     // [8, 10]
                 const float* __restrict__ ob,     // [10]
                 float* __restrict__ out)          // [B, 10]
{
    // Row k occupies sW2[k*8 .. k*8+7]; quad q holds gate columns 4q..4q+3.
    __shared__ ulonglong2 sW2[(INDIM + HID) * 8];   // 36 rows * 128B
    __shared__ ulonglong2 sB2[8];
    __shared__ float sOW[HID * NCLS];
    __shared__ float sOB[NCLS];

    const int tid = threadIdx.x;
    {
        const u64* gW = (const u64*)W;
        u64* sw = (u64*)sW2;
        for (int i = tid; i < (INDIM + HID) * 16; i += BLK) sw[i] = gW[i];
        for (int i = tid; i < 16; i += BLK)         ((u64*)sB2)[i] = ((const u64*)bias)[i];
        for (int i = tid; i < HID * NCLS; i += BLK) sOW[i] = ow[i];
        for (int i = tid; i < NCLS; i += BLK)       sOB[i] = ob[i];
    }
    __syncthreads();

    const int gtid   = blockIdx.x * BLK + tid;
    const int sample = gtid >> 1;        // lanes 2k, 2k+1 = same sample
    const int m      = gtid & 1;         // 0: i,j half (cols 0..15); 1: f,o half (16..31)

    // Per-lane activation constants (uniform control flow):
    //  A-gate (first 8 cols of this half): sigma(first + fbias)
    //  B-gate (last 8 cols):  m=0 -> tanh(x): e=exp(2x), B = 1 - 2/(e+1)
    //                         m=1 -> sigma(x): e=exp(-x), B = 1/(e+1)
    const float fbias = m ? 1.0f : 0.0f;         // forget bias (f = first half of odd lane)
    const float kB    = m ? -1.0f : 2.0f;
    const float cB    = m ?  1.0f : -2.0f;
    const float dB    = m ?  0.0f :  1.0f;

    const float4* xp = (const float4*)(x + (size_t)sample * TSTEPS * INDIM);  // 7 float4/step

    float c[HID];
#pragma unroll
    for (int u = 0; u < HID; u++) c[u] = 0.0f;
    float4 hA = make_float4(0, 0, 0, 0);   // h0..h3
    float4 hB = make_float4(0, 0, 0, 0);   // h4..h7

    const u64* sBu = (const u64*)sB2;

#pragma unroll 1
    for (int t = 0; t < TSTEPS; t++) {
        // 8 u64 accumulators = this lane's 16 gate columns, init with bias.
        u64 g[8];
#pragma unroll
        for (int i = 0; i < 8; i++) g[i] = sBu[8 * m + i];

        float4 cur = xp[t * 7];

        // 9 segments: 0..6 -> x chunks (rows 4s..4s+3), 7 -> hA (28..31), 8 -> hB (32..35)
#pragma unroll 1
        for (int seg = 0; seg < 9; seg++) {
            float4 nxt;
            if (seg < 6)       nxt = xp[t * 7 + seg + 1];
            else if (seg == 6) nxt = hA;
            else if (seg == 7) nxt = hB;
            else               nxt = cur;   // dead

            const int krow = 4 * seg;
#pragma unroll
            for (int j = 0; j < 4; j++) {
                float xs = (j == 0) ? cur.x : (j == 1) ? cur.y : (j == 2) ? cur.z : cur.w;
                u64 xx = pack2(xs);
                const int rowbase = (krow + j) * 8 + 4 * m;   // this lane's 4 quads
#pragma unroll
                for (int qq = 0; qq < 4; qq++) {
                    ulonglong2 w = sW2[rowbase + qq];
                    g[2 * qq]     = fma2(xx, w.x, g[2 * qq]);
                    g[2 * qq + 1] = fma2(xx, w.y, g[2 * qq + 1]);
                }
            }
            cur = nxt;
        }

        // Unpack: first[u] = col 16m+u (i or f), second[u] = col 16m+8+u (j or o)
        float first[8], second[8];
#pragma unroll
        for (int v = 0; v < 4; v++) {
            unpack2(g[v],     first[2 * v],  first[2 * v + 1]);
            unpack2(g[4 + v], second[2 * v], second[2 * v + 1]);
        }

        float A[8], Bv[8];
#pragma unroll
        for (int u = 0; u < HID; u++) {
            // A = sigma(first + fbias)
            float ea = __expf(-(first[u] + fbias));
            A[u] = __fdividef(1.0f, 1.0f + ea);
            // B = cB * 1/(exp(kB*x)+1) + dB   (tanh for m=0, sigma for m=1)
            float eb = __expf(kB * second[u]);
            float r  = __fdividef(1.0f, eb + 1.0f);
            Bv[u] = cB * r + dB;
        }

        // Exchange halves: partner's A,B via shfl.xor(1). Then both lanes
        // compute identical c,h (same values, same op order -> bit-identical).
        float hn[8];
#pragma unroll
        for (int u = 0; u < HID; u++) {
            float pA = __shfl_xor_sync(0xffffffffu, A[u], 1);
            float pB = __shfl_xor_sync(0xffffffffu, Bv[u], 1);
            float ig = m ? pA : A[u];     // sigma(i)
            float jt = m ? pB : Bv[u];    // tanh(j)
            float fg = m ? A[u] : pA;     // sigma(f+1)
            float og = m ? Bv[u] : pB;    // sigma(o)
            float cn = c[u] * fg + ig * jt;
            c[u] = cn;
            hn[u] = tanh_exact(cn) * og;
        }
        hA = make_float4(hn[0], hn[1], hn[2], hn[3]);
        hB = make_float4(hn[4], hn[5], hn[6], hn[7]);
    }

    // Output projection (even lane only): logits = h @ ow + ob
    if (m == 0) {
        float hf[8] = {hA.x, hA.y, hA.z, hA.w, hB.x, hB.y, hB.z, hB.w};
        float* op = out + (size_t)sample * NCLS;
#pragma unroll
        for (int n = 0; n < NCLS; n++) {
            float acc = sOB[n];
#pragma unroll
            for (int u = 0; u < HID; u++) acc += hf[u] * sOW[u * NCLS + n];
            op[n] = acc;
        }
    }
}

extern "C" void kernel_launch(void* const* d_in, const int* in_sizes, int n_in,
                              void* d_out, int out_size) {
    const float* x  = (const float*)d_in[0];
    const float* W  = (const float*)d_in[1];
    const float* bl = (const float*)d_in[2];
    const float* ow = (const float*)d_in[3];
    const float* ob = (const float*)d_in[4];
    float* out = (float*)d_out;

    // 2 lanes per sample -> 65536 threads
    lstm_kernel<<<(BTOT * 2) / BLK, BLK>>>(x, W, bl, ow, ob, out);
}